// round 7
// baseline (speedup 1.0000x reference)
#include <cuda_runtime.h>
#include <cuda_bf16.h>
#include <math.h>
#include <stdint.h>

// ---------------- problem constants ----------------
#define BB 2
#define SS 2048
#define DD 1024
#define HH 16
#define HD 64
#define LL 8
#define VV 32000
#define MM (BB*SS)          // 4096 rows
#define QKVS (3*DD)
#define FFS  (2*DD)

// ---------------- weight plane offsets ----------------
#define WMAT (DD*DD)
#define QKV_OFF 0                       // 3L*WMAT, layer stride 3*WMAT (q,k,v rows)
#define WO_OFF  (3*LL*WMAT)
#define W13_OFF (4*LL*WMAT)             // layer stride 2*WMAT (w1, w3 rows)
#define W2_OFF  (6*LL*WMAT)
#define WOUT_OFF (7*LL*WMAT)
#define WTOT (WOUT_OFF + VV*DD)

// ---------------- scratch (device globals) ----------
__device__ float g_x[MM*DD];
__device__ __nv_bfloat16 g_whi[WTOT];
__device__ __nv_bfloat16 g_wlo[WTOT];
__device__ __nv_bfloat16 g_ahi[MM*DD];
__device__ __nv_bfloat16 g_alo[MM*DD];
__device__ __nv_bfloat16 g_qkvh[MM*QKVS];
__device__ __nv_bfloat16 g_qkvl[MM*QKVS];
__device__ __nv_bfloat16 g_ffh[MM*FFS];
__device__ __nv_bfloat16 g_ffl[MM*FFS];

// ================= helpers =================
__device__ __forceinline__ uint32_t smem_u32(const void* p) {
    uint32_t a;
    asm("{ .reg .u64 t; cvta.to.shared.u64 t, %1; cvt.u32.u64 %0, t; }"
        : "=r"(a) : "l"(p));
    return a;
}
#define CP16(dst, src) \
    asm volatile("cp.async.cg.shared.global [%0], [%1], 16;" :: "r"(dst), "l"(src))
#define CP_COMMIT() asm volatile("cp.async.commit_group;" ::: "memory")
#define CP_WAIT1()  asm volatile("cp.async.wait_group 1;" ::: "memory")
#define CP_WAIT0()  asm volatile("cp.async.wait_group 0;" ::: "memory")
#define LDSM4(r, addr) \
    asm volatile("ldmatrix.sync.aligned.m8n8.x4.shared.b16 {%0,%1,%2,%3}, [%4];" \
        : "=r"((r)[0]), "=r"((r)[1]), "=r"((r)[2]), "=r"((r)[3]) : "r"(addr))
#define MMA16816(c, a, b0v, b1v) \
    asm volatile("mma.sync.aligned.m16n8k16.row.col.f32.bf16.bf16.f32 " \
        "{%0,%1,%2,%3}, {%4,%5,%6,%7}, {%8,%9}, {%0,%1,%2,%3};" \
        : "+f"((c)[0]), "+f"((c)[1]), "+f"((c)[2]), "+f"((c)[3]) \
        : "r"((a)[0]), "r"((a)[1]), "r"((a)[2]), "r"((a)[3]), "r"(b0v), "r"(b1v))

__device__ __forceinline__ void split1(float x, __nv_bfloat16& h, __nv_bfloat16& l) {
    h = __float2bfloat16(x);
    l = __float2bfloat16(x - __bfloat162float(h));
}
__device__ __forceinline__ uint32_t pack_hi2(float a, float b) {
    __nv_bfloat162 p = __floats2bfloat162_rn(a, b);
    return *(uint32_t*)&p;
}

// ---------------- fp32 -> (hi, lo) bf16 split (weights) ----------------
__global__ void conv_split(const float* __restrict__ src,
                           __nv_bfloat16* __restrict__ hi,
                           __nv_bfloat16* __restrict__ lo, int n4) {
    int i = blockIdx.x * 256 + threadIdx.x;
    if (i >= n4) return;
    float4 v = ((const float4*)src)[i];
    __nv_bfloat16 h0, h1, h2, h3, l0, l1, l2, l3;
    split1(v.x, h0, l0); split1(v.y, h1, l1);
    split1(v.z, h2, l2); split1(v.w, h3, l3);
    ((ushort4*)hi)[i] = make_ushort4(__bfloat16_as_ushort(h0), __bfloat16_as_ushort(h1),
                                     __bfloat16_as_ushort(h2), __bfloat16_as_ushort(h3));
    ((ushort4*)lo)[i] = make_ushort4(__bfloat16_as_ushort(l0), __bfloat16_as_ushort(l1),
                                     __bfloat16_as_ushort(l2), __bfloat16_as_ushort(l3));
}

// ================= mma.sync split-bf16 GEMM =================
// C[M,N] = A[M,K] @ W[N,K]^T. 128x128 tile, BK=32, 128 thr (4 warps, 64x64 each).
#define PLANE_B 10240
#define STAGE_B (4*PLANE_B)
#define GSMEM   (2*STAGE_B)

template<bool RESID, bool SPLITOUT>
__global__ void __launch_bounds__(128, 2)
gemm_mma(const __nv_bfloat16* __restrict__ Ahi, const __nv_bfloat16* __restrict__ Alo,
         const __nv_bfloat16* __restrict__ Bhi, const __nv_bfloat16* __restrict__ Blo,
         const float* __restrict__ R, float* __restrict__ C,
         __nv_bfloat16* __restrict__ Chi, __nv_bfloat16* __restrict__ Clo,
         int N, int K) {
    extern __shared__ char sm_raw[];
    uint32_t sb = smem_u32(sm_raw);
    int tid = threadIdx.x, lane = tid & 31, w = tid >> 5;
    int wm = w & 1, wn = w >> 1;
    int m0 = blockIdx.y * 128, n0 = blockIdx.x * 128;
    const __nv_bfloat16* srcs[4] = {Ahi, Alo, Bhi, Blo};
    int nslab = K / 32;

    {   // prologue: each thread loads one row (64B) per plane
        #pragma unroll
        for (int p = 0; p < 4; p++) {
            int rb = (p < 2) ? m0 : n0;
            const __nv_bfloat16* g = srcs[p] + (size_t)(rb + tid) * K;
            uint32_t d = sb + p * PLANE_B + tid * 80;
            CP16(d, g); CP16(d + 16, g + 8);
            CP16(d + 32, g + 16); CP16(d + 48, g + 24);
        }
        CP_COMMIT();
    }

    float acc[4][8][4] = {};
    int gq = lane >> 3, rr = lane & 7;

    for (int s = 0; s < nslab; s++) {
        if (s + 1 < nslab) {
            uint32_t stb = sb + ((s + 1) & 1) * STAGE_B;
            int k0 = (s + 1) * 32;
            #pragma unroll
            for (int p = 0; p < 4; p++) {
                int rb = (p < 2) ? m0 : n0;
                const __nv_bfloat16* g = srcs[p] + (size_t)(rb + tid) * K + k0;
                uint32_t d = stb + p * PLANE_B + tid * 80;
                CP16(d, g); CP16(d + 16, g + 8);
                CP16(d + 32, g + 16); CP16(d + 48, g + 24);
            }
            CP_COMMIT();
            CP_WAIT1();
        } else {
            CP_WAIT0();
        }
        __syncthreads();

        uint32_t stb = sb + (s & 1) * STAGE_B;
        #pragma unroll
        for (int ks = 0; ks < 2; ks++) {
            uint32_t ah[4][4], al[4][4];
            #pragma unroll
            for (int mf = 0; mf < 4; mf++) {
                int row = wm * 64 + mf * 16 + (gq & 1) * 8 + rr;
                int col = ks * 16 + (gq >> 1) * 8;
                uint32_t a = stb + row * 80 + col * 2;
                LDSM4(ah[mf], a);
                LDSM4(al[mf], a + PLANE_B);
            }
            #pragma unroll
            for (int np = 0; np < 4; np++) {
                uint32_t bh[4], bl[4];
                int row = wn * 64 + np * 16 + (gq >> 1) * 8 + rr;
                int col = ks * 16 + (gq & 1) * 8;
                uint32_t a = stb + 2 * PLANE_B + row * 80 + col * 2;
                LDSM4(bh, a);
                LDSM4(bl, a + PLANE_B);
                #pragma unroll
                for (int mf = 0; mf < 4; mf++) {
                    MMA16816(acc[mf][np*2],   ah[mf], bh[0], bh[1]);
                    MMA16816(acc[mf][np*2],   al[mf], bh[0], bh[1]);
                    MMA16816(acc[mf][np*2],   ah[mf], bl[0], bl[1]);
                    MMA16816(acc[mf][np*2+1], ah[mf], bh[2], bh[3]);
                    MMA16816(acc[mf][np*2+1], al[mf], bh[2], bh[3]);
                    MMA16816(acc[mf][np*2+1], ah[mf], bl[2], bl[3]);
                }
            }
        }
        __syncthreads();
    }

    int rbase = m0 + wm * 64 + (lane >> 2);
    int cbase = n0 + wn * 64 + (lane & 3) * 2;
    #pragma unroll
    for (int mf = 0; mf < 4; mf++) {
        #pragma unroll
        for (int nf = 0; nf < 8; nf++) {
            int row = rbase + mf * 16;
            int col = cbase + nf * 8;
            float v0 = acc[mf][nf][0], v1 = acc[mf][nf][1];
            float v2 = acc[mf][nf][2], v3 = acc[mf][nf][3];
            size_t a0 = (size_t)row * N + col;
            size_t a1 = (size_t)(row + 8) * N + col;
            if (SPLITOUT) {
                __nv_bfloat16 h0,h1,h2,h3,L0,L1,L2,L3;
                split1(v0, h0, L0); split1(v1, h1, L1);
                split1(v2, h2, L2); split1(v3, h3, L3);
                *(__nv_bfloat162*)(Chi + a0) = __halves2bfloat162(h0, h1);
                *(__nv_bfloat162*)(Clo + a0) = __halves2bfloat162(L0, L1);
                *(__nv_bfloat162*)(Chi + a1) = __halves2bfloat162(h2, h3);
                *(__nv_bfloat162*)(Clo + a1) = __halves2bfloat162(L2, L3);
            } else {
                if (RESID) {
                    float2 r0 = *(const float2*)(R + a0);
                    float2 r1 = *(const float2*)(R + a1);
                    v0 += r0.x; v1 += r0.y; v2 += r1.x; v3 += r1.y;
                }
                *(float2*)(C + a0) = make_float2(v0, v1);
                *(float2*)(C + a1) = make_float2(v2, v3);
            }
        }
    }
}

// ================= mma.sync flash attention (split-bf16 plane inputs) =====
#define ALD 72
#define APLANE (64*ALD*2)
#define ASMEM  (6*APLANE)

__global__ void __launch_bounds__(128)
attn_mma(const __nv_bfloat16* __restrict__ Ph, const __nv_bfloat16* __restrict__ Pl,
         __nv_bfloat16* __restrict__ Ohi, __nv_bfloat16* __restrict__ Olo) {
    extern __shared__ char asmr[];
    uint32_t sb = smem_u32(asmr);
    const uint32_t QH = sb, QL = sb + APLANE, KH = sb + 2*APLANE,
                   KL = sb + 3*APLANE, VH = sb + 4*APLANE, VL = sb + 5*APLANE;

    int tid = threadIdx.x, lane = tid & 31, w = tid >> 5;
    int gq = lane >> 3, rr = lane & 7;
    int bh = blockIdx.y;
    int b = bh / HH, h = bh % HH;
    int qt = blockIdx.x;
    float slope = exp2f(-0.5f * (float)(h + 1));

    int lrow = tid >> 4;          // 0..7
    int lcol = (tid & 15) * 4;    // 0..60

    // ---- load Q tile (exact x0.125 scale on bf16 planes) ----
    __nv_bfloat162 sc2 = __float2bfloat162_rn(0.125f);
    #pragma unroll
    for (int pass = 0; pass < 8; pass++) {
        int row = lrow + pass * 8;
        size_t ga = (size_t)(b*SS + qt*64 + row) * QKVS + h*HD + lcol;
        uint2 qh2 = *(const uint2*)(Ph + ga);
        uint2 ql2 = *(const uint2*)(Pl + ga);
        __nv_bfloat162 a0 = __hmul2(*(__nv_bfloat162*)&qh2.x, sc2);
        __nv_bfloat162 a1 = __hmul2(*(__nv_bfloat162*)&qh2.y, sc2);
        __nv_bfloat162 b0 = __hmul2(*(__nv_bfloat162*)&ql2.x, sc2);
        __nv_bfloat162 b1 = __hmul2(*(__nv_bfloat162*)&ql2.y, sc2);
        uint32_t off = (row*ALD + lcol) * 2;
        *(uint2*)(asmr + (QH - sb) + off) = make_uint2(*(uint32_t*)&a0, *(uint32_t*)&a1);
        *(uint2*)(asmr + (QL - sb) + off) = make_uint2(*(uint32_t*)&b0, *(uint32_t*)&b1);
    }
    __syncthreads();

    uint32_t qh[4][4], ql[4][4];
    #pragma unroll
    for (int kk = 0; kk < 4; kk++) {
        uint32_t off = ((w*16 + (gq & 1)*8 + rr)*ALD + kk*16 + (gq >> 1)*8) * 2;
        LDSM4(qh[kk], QH + off);
        LDSM4(ql[kk], QL + off);
    }

    float m0r = -INFINITY, m1r = -INFINITY, l0s = 0.f, l1s = 0.f;
    float o[8][4] = {};
    int qg0 = qt*64 + w*16 + (lane >> 2);
    int qg1 = qg0 + 8;

    for (int kt = 0; kt <= qt; kt++) {
        __syncthreads();
        #pragma unroll
        for (int pass = 0; pass < 8; pass++) {
            int row = lrow + pass * 8;
            size_t gr = (size_t)(b*SS + kt*64 + row) * QKVS + h*HD + lcol;
            uint2 kh2 = *(const uint2*)(Ph + gr + DD);
            uint2 kl2 = *(const uint2*)(Pl + gr + DD);
            uint32_t off = (row*ALD + lcol) * 2;
            *(uint2*)(asmr + (KH - sb) + off) = kh2;
            *(uint2*)(asmr + (KL - sb) + off) = kl2;
            uint2 vh2 = *(const uint2*)(Ph + gr + 2*DD);
            uint2 vl2 = *(const uint2*)(Pl + gr + 2*DD);
            const __nv_bfloat16* vh = (const __nv_bfloat16*)&vh2;
            const __nv_bfloat16* vl = (const __nv_bfloat16*)&vl2;
            #pragma unroll
            for (int i = 0; i < 4; i++) {
                uint32_t toff = ((lcol + i)*ALD + row) * 2;
                *(__nv_bfloat16*)(asmr + (VH - sb) + toff) = vh[i];
                *(__nv_bfloat16*)(asmr + (VL - sb) + toff) = vl[i];
            }
        }
        __syncthreads();

        // ---- S = Q @ K^T ----
        float s[8][4] = {};
        #pragma unroll
        for (int kk = 0; kk < 4; kk++) {
            #pragma unroll
            for (int np = 0; np < 4; np++) {
                uint32_t kb[4], kl2[4];
                uint32_t off = ((np*16 + (gq >> 1)*8 + rr)*ALD + kk*16 + (gq & 1)*8) * 2;
                LDSM4(kb, KH + off);
                LDSM4(kl2, KL + off);
                MMA16816(s[np*2],   qh[kk], kb[0], kb[1]);
                MMA16816(s[np*2],   ql[kk], kb[0], kb[1]);
                MMA16816(s[np*2],   qh[kk], kl2[0], kl2[1]);
                MMA16816(s[np*2+1], qh[kk], kb[2], kb[3]);
                MMA16816(s[np*2+1], ql[kk], kb[2], kb[3]);
                MMA16816(s[np*2+1], qh[kk], kl2[2], kl2[3]);
            }
        }

        // ---- ALiBi bias + causal mask ----
        #pragma unroll
        for (int nf = 0; nf < 8; nf++) {
            #pragma unroll
            for (int c = 0; c < 2; c++) {
                int kg = kt*64 + nf*8 + (lane & 3)*2 + c;
                s[nf][c]   = (kg <= qg0) ? s[nf][c]   + slope*(float)(kg - qg0) : -1e30f;
                s[nf][2+c] = (kg <= qg1) ? s[nf][2+c] + slope*(float)(kg - qg1) : -1e30f;
            }
        }

        // ---- online softmax ----
        float mx0 = -1e30f, mx1 = -1e30f;
        #pragma unroll
        for (int nf = 0; nf < 8; nf++) {
            mx0 = fmaxf(mx0, fmaxf(s[nf][0], s[nf][1]));
            mx1 = fmaxf(mx1, fmaxf(s[nf][2], s[nf][3]));
        }
        #pragma unroll
        for (int off = 1; off <= 2; off <<= 1) {
            mx0 = fmaxf(mx0, __shfl_xor_sync(0xffffffffu, mx0, off));
            mx1 = fmaxf(mx1, __shfl_xor_sync(0xffffffffu, mx1, off));
        }
        float mn0 = fmaxf(m0r, mx0), mn1 = fmaxf(m1r, mx1);
        float al0 = __expf(m0r - mn0), al1 = __expf(m1r - mn1);
        float rs0 = 0.f, rs1 = 0.f;
        #pragma unroll
        for (int nf = 0; nf < 8; nf++) {
            s[nf][0] = __expf(s[nf][0] - mn0);
            s[nf][1] = __expf(s[nf][1] - mn0);
            s[nf][2] = __expf(s[nf][2] - mn1);
            s[nf][3] = __expf(s[nf][3] - mn1);
            rs0 += s[nf][0] + s[nf][1];
            rs1 += s[nf][2] + s[nf][3];
        }
        #pragma unroll
        for (int off = 1; off <= 2; off <<= 1) {
            rs0 += __shfl_xor_sync(0xffffffffu, rs0, off);
            rs1 += __shfl_xor_sync(0xffffffffu, rs1, off);
        }
        l0s = l0s * al0 + rs0;
        l1s = l1s * al1 + rs1;
        m0r = mn0; m1r = mn1;

        #pragma unroll
        for (int nf = 0; nf < 8; nf++) {
            o[nf][0] *= al0; o[nf][1] *= al0;
            o[nf][2] *= al1; o[nf][3] *= al1;
        }

        // ---- O += P @ V (P split on the fly) ----
        #pragma unroll
        for (int kk = 0; kk < 4; kk++) {
            uint32_t Ah[4], Al2[4];
            #pragma unroll
            for (int half = 0; half < 2; half++) {
                float* sv = s[2*kk + half];
                __nv_bfloat162 h01 = __floats2bfloat162_rn(sv[0], sv[1]);
                __nv_bfloat162 h23 = __floats2bfloat162_rn(sv[2], sv[3]);
                __nv_bfloat162 L01 = __floats2bfloat162_rn(
                    sv[0] - __bfloat162float(__low2bfloat16(h01)),
                    sv[1] - __bfloat162float(__high2bfloat16(h01)));
                __nv_bfloat162 L23 = __floats2bfloat162_rn(
                    sv[2] - __bfloat162float(__low2bfloat16(h23)),
                    sv[3] - __bfloat162float(__high2bfloat16(h23)));
                Ah[half*2 + 0] = *(uint32_t*)&h01;
                Ah[half*2 + 1] = *(uint32_t*)&h23;
                Al2[half*2 + 0] = *(uint32_t*)&L01;
                Al2[half*2 + 1] = *(uint32_t*)&L23;
            }
            #pragma unroll
            for (int np = 0; np < 4; np++) {
                uint32_t vb[4], vl2[4];
                uint32_t off = ((np*16 + (gq >> 1)*8 + rr)*ALD + kk*16 + (gq & 1)*8) * 2;
                LDSM4(vb, VH + off);
                LDSM4(vl2, VL + off);
                MMA16816(o[np*2],   Ah,  vb[0], vb[1]);
                MMA16816(o[np*2],   Al2, vb[0], vb[1]);
                MMA16816(o[np*2],   Ah,  vl2[0], vl2[1]);
                MMA16816(o[np*2+1], Ah,  vb[2], vb[3]);
                MMA16816(o[np*2+1], Al2, vb[2], vb[3]);
                MMA16816(o[np*2+1], Ah,  vl2[2], vl2[3]);
            }
        }
    }

    // ---- epilogue ----
    float inv0 = 1.f / l0s, inv1 = 1.f / l1s;
    int row0 = b*SS + qt*64 + w*16 + (lane >> 2);
    int colb = h*HD + (lane & 3)*2;
    #pragma unroll
    for (int nf = 0; nf < 8; nf++) {
        float v0 = o[nf][0]*inv0, v1 = o[nf][1]*inv0;
        float v2 = o[nf][2]*inv1, v3 = o[nf][3]*inv1;
        size_t a0 = (size_t)row0 * DD + colb + nf*8;
        size_t a1 = (size_t)(row0 + 8) * DD + colb + nf*8;
        __nv_bfloat16 h0,h1,h2,h3,L0,L1,L2,L3;
        split1(v0, h0, L0); split1(v1, h1, L1);
        split1(v2, h2, L2); split1(v3, h3, L3);
        *(__nv_bfloat162*)(Ohi + a0) = __halves2bfloat162(h0, h1);
        *(__nv_bfloat162*)(Olo + a0) = __halves2bfloat162(L0, L1);
        *(__nv_bfloat162*)(Ohi + a1) = __halves2bfloat162(h2, h3);
        *(__nv_bfloat162*)(Olo + a1) = __halves2bfloat162(L2, L3);
    }
}

// ---------------- embedding lookup ----------------
__global__ void embed_kernel(const int* __restrict__ tokens,
                             const float* __restrict__ emb,
                             float* __restrict__ x) {
    int row = blockIdx.x;
    int tok = tokens[row];
    const float4* src = (const float4*)(emb + (size_t)tok * DD);
    float4* dst = (float4*)(x + (size_t)row * DD);
    for (int i = threadIdx.x; i < DD/4; i += blockDim.x) dst[i] = src[i];
}

// ---------------- layernorm -> bf16 hi/lo planes ----------------
__global__ void ln_kernel(const float* __restrict__ x,
                          const float* __restrict__ gw,
                          const float* __restrict__ bw,
                          __nv_bfloat16* __restrict__ hi,
                          __nv_bfloat16* __restrict__ lo) {
    int row = blockIdx.x;
    const float* xr = x + (size_t)row * DD;
    float s = 0.f, s2 = 0.f;
    for (int i = threadIdx.x; i < DD; i += 256) {
        float v = xr[i];
        s += v;
        s2 = fmaf(v, v, s2);
    }
    __shared__ float rs[8], rs2[8];
    #pragma unroll
    for (int o = 16; o > 0; o >>= 1) {
        s  += __shfl_down_sync(0xffffffffu, s,  o);
        s2 += __shfl_down_sync(0xffffffffu, s2, o);
    }
    int w = threadIdx.x >> 5;
    if ((threadIdx.x & 31) == 0) { rs[w] = s; rs2[w] = s2; }
    __syncthreads();
    __shared__ float mean_s, rstd_s;
    if (threadIdx.x == 0) {
        float ts = 0.f, ts2 = 0.f;
        #pragma unroll
        for (int i = 0; i < 8; i++) { ts += rs[i]; ts2 += rs2[i]; }
        float m = ts / (float)DD;
        float var = ts2 / (float)DD - m * m;
        mean_s = m;
        rstd_s = rsqrtf(var + 1e-5f);
    }
    __syncthreads();
    float m = mean_s, r = rstd_s;
    __nv_bfloat16* hrow = hi + (size_t)row * DD;
    __nv_bfloat16* lrow = lo + (size_t)row * DD;
    for (int i = threadIdx.x; i < DD; i += 256) {
        float v = (xr[i] - m) * r * gw[i] + bw[i];
        __nv_bfloat16 vh, vl;
        split1(v, vh, vl);
        hrow[i] = vh;
        lrow[i] = vl;
    }
}

// ---------------- SwiGLU from packed ff planes -> bf16 hi/lo --------------
__global__ void swiglu_kernel(const __nv_bfloat16* __restrict__ fh,
                              const __nv_bfloat16* __restrict__ fl,
                              __nv_bfloat16* __restrict__ hi,
                              __nv_bfloat16* __restrict__ lo) {
    int i = blockIdx.x * 256 + threadIdx.x;   // over MM*DD/4 quads
    int row = i / (DD/4);
    int c4 = (i % (DD/4)) * 4;
    size_t fa = (size_t)row * FFS + c4;
    ushort4 ah4 = *(const ushort4*)(fh + fa);
    ushort4 al4 = *(const ushort4*)(fl + fa);
    ushort4 ch4 = *(const ushort4*)(fh + fa + DD);
    ushort4 cl4 = *(const ushort4*)(fl + fa + DD);
    float x0 = __bfloat162float(__ushort_as_bfloat16(ah4.x)) + __bfloat162float(__ushort_as_bfloat16(al4.x));
    float x1 = __bfloat162float(__ushort_as_bfloat16(ah4.y)) + __bfloat162float(__ushort_as_bfloat16(al4.y));
    float x2 = __bfloat162float(__ushort_as_bfloat16(ah4.z)) + __bfloat162float(__ushort_as_bfloat16(al4.z));
    float x3 = __bfloat162float(__ushort_as_bfloat16(ah4.w)) + __bfloat162float(__ushort_as_bfloat16(al4.w));
    float c0 = __bfloat162float(__ushort_as_bfloat16(ch4.x)) + __bfloat162float(__ushort_as_bfloat16(cl4.x));
    float c1 = __bfloat162float(__ushort_as_bfloat16(ch4.y)) + __bfloat162float(__ushort_as_bfloat16(cl4.y));
    float c2 = __bfloat162float(__ushort_as_bfloat16(ch4.z)) + __bfloat162float(__ushort_as_bfloat16(cl4.z));
    float c3 = __bfloat162float(__ushort_as_bfloat16(ch4.w)) + __bfloat162float(__ushort_as_bfloat16(cl4.w));
    float r0 = x0 / (1.f + __expf(-x0)) * c0;
    float r1 = x1 / (1.f + __expf(-x1)) * c1;
    float r2 = x2 / (1.f + __expf(-x2)) * c2;
    float r3 = x3 / (1.f + __expf(-x3)) * c3;
    __nv_bfloat16 h0,h1,h2,h3,l0,l1,l2,l3;
    split1(r0, h0, l0); split1(r1, h1, l1);
    split1(r2, h2, l2); split1(r3, h3, l3);
    size_t oa = (size_t)row * DD + c4;
    *(ushort4*)(hi + oa) = make_ushort4(__bfloat16_as_ushort(h0), __bfloat16_as_ushort(h1),
                                        __bfloat16_as_ushort(h2), __bfloat16_as_ushort(h3));
    *(ushort4*)(lo + oa) = make_ushort4(__bfloat16_as_ushort(l0), __bfloat16_as_ushort(l1),
                                        __bfloat16_as_ushort(l2), __bfloat16_as_ushort(l3));
}

// ---------------- launch ----------------
extern "C" void kernel_launch(void* const* d_in, const int* in_sizes, int n_in,
                              void* d_out, int out_size) {
    const int*   tokens = (const int*)d_in[0];
    const float* emb    = (const float*)d_in[1];
    const float* wq     = (const float*)d_in[2];
    const float* wk     = (const float*)d_in[3];
    const float* wv     = (const float*)d_in[4];
    const float* wo     = (const float*)d_in[5];
    const float* ln1_g  = (const float*)d_in[6];
    const float* ln1_b  = (const float*)d_in[7];
    const float* ln2_g  = (const float*)d_in[8];
    const float* ln2_b  = (const float*)d_in[9];
    const float* w1     = (const float*)d_in[10];
    const float* w2     = (const float*)d_in[11];
    const float* w3     = (const float*)d_in[12];
    const float* lnf_g  = (const float*)d_in[13];
    const float* lnf_b  = (const float*)d_in[14];
    const float* w_out  = (const float*)d_in[15];
    float* out = (float*)d_out;

    float* px;
    cudaGetSymbolAddress((void**)&px, g_x);
    __nv_bfloat16 *whi, *wlo, *ahi, *alo, *qkvh, *qkvl, *ffh, *ffl;
    cudaGetSymbolAddress((void**)&whi, g_whi);
    cudaGetSymbolAddress((void**)&wlo, g_wlo);
    cudaGetSymbolAddress((void**)&ahi, g_ahi);
    cudaGetSymbolAddress((void**)&alo, g_alo);
    cudaGetSymbolAddress((void**)&qkvh, g_qkvh);
    cudaGetSymbolAddress((void**)&qkvl, g_qkvl);
    cudaGetSymbolAddress((void**)&ffh, g_ffh);
    cudaGetSymbolAddress((void**)&ffl, g_ffl);

    cudaFuncSetAttribute(attn_mma,
                         cudaFuncAttributeMaxDynamicSharedMemorySize, ASMEM);
    cudaFuncSetAttribute(gemm_mma<false,true>,
                         cudaFuncAttributeMaxDynamicSharedMemorySize, GSMEM);
    cudaFuncSetAttribute(gemm_mma<true,false>,
                         cudaFuncAttributeMaxDynamicSharedMemorySize, GSMEM);
    cudaFuncSetAttribute(gemm_mma<false,false>,
                         cudaFuncAttributeMaxDynamicSharedMemorySize, GSMEM);

    // ---- convert weights to bf16 hi/lo planes (packed layouts) ----
    {
        int n4 = WMAT / 4;
        for (int l = 0; l < LL; l++) {
            size_t so = (size_t)l * WMAT;
            size_t qo = QKV_OFF + (size_t)l * 3 * WMAT;
            conv_split<<<n4/256, 256>>>(wq + so, whi + qo,            wlo + qo,            n4);
            conv_split<<<n4/256, 256>>>(wk + so, whi + qo + WMAT,     wlo + qo + WMAT,     n4);
            conv_split<<<n4/256, 256>>>(wv + so, whi + qo + 2*WMAT,   wlo + qo + 2*WMAT,   n4);
            size_t fo = W13_OFF + (size_t)l * 2 * WMAT;
            conv_split<<<n4/256, 256>>>(w1 + so, whi + fo,            wlo + fo,            n4);
            conv_split<<<n4/256, 256>>>(w3 + so, whi + fo + WMAT,     wlo + fo + WMAT,     n4);
        }
        int n4L = (LL * WMAT) / 4;
        conv_split<<<n4L/256, 256>>>(wo, whi + WO_OFF, wlo + WO_OFF, n4L);
        conv_split<<<n4L/256, 256>>>(w2, whi + W2_OFF, wlo + W2_OFF, n4L);
        int n4o = (VV * DD) / 4;
        conv_split<<<n4o/256, 256>>>(w_out, whi + WOUT_OFF, wlo + WOUT_OFF, n4o);
    }

    embed_kernel<<<MM, 256>>>(tokens, emb, px);

    dim3 gQKV(QKVS/128, MM/128);
    dim3 gD(DD/128, MM/128);
    dim3 gFF(FFS/128, MM/128);
    for (int l = 0; l < LL; l++) {
        size_t qo = QKV_OFF + (size_t)l * 3 * WMAT;
        size_t oo = WO_OFF + (size_t)l * WMAT;
        size_t fo = W13_OFF + (size_t)l * 2 * WMAT;
        size_t to = W2_OFF + (size_t)l * WMAT;

        // attention
        ln_kernel<<<MM, 256>>>(px, ln1_g + l*DD, ln1_b + l*DD, ahi, alo);
        gemm_mma<false,true><<<gQKV, 128, GSMEM>>>(ahi, alo, whi + qo, wlo + qo,
                                                   nullptr, nullptr, qkvh, qkvl, QKVS, DD);
        attn_mma<<<dim3(SS/64, BB*HH), 128, ASMEM>>>(qkvh, qkvl, ahi, alo);
        gemm_mma<true,false><<<gD, 128, GSMEM>>>(ahi, alo, whi + oo, wlo + oo,
                                                 px, px, nullptr, nullptr, DD, DD);

        // SwiGLU FFN
        ln_kernel<<<MM, 256>>>(px, ln2_g + l*DD, ln2_b + l*DD, ahi, alo);
        gemm_mma<false,true><<<gFF, 128, GSMEM>>>(ahi, alo, whi + fo, wlo + fo,
                                                  nullptr, nullptr, ffh, ffl, FFS, DD);
        swiglu_kernel<<<(MM*DD/4)/256, 256>>>(ffh, ffl, ahi, alo);
        gemm_mma<true,false><<<gD, 128, GSMEM>>>(ahi, alo, whi + to, wlo + to,
                                                 px, px, nullptr, nullptr, DD, DD);
    }

    // final LN + logits
    ln_kernel<<<MM, 256>>>(px, lnf_g, lnf_b, ahi, alo);
    gemm_mma<false,false><<<dim3(VV/128, MM/128), 128, GSMEM>>>(
        ahi, alo, whi + WOUT_OFF, wlo + WOUT_OFF, nullptr, out, nullptr, nullptr, VV, DD);
}

// round 9
// speedup vs baseline: 1.1469x; 1.1469x over previous
#include <cuda_runtime.h>
#include <cuda_bf16.h>
#include <math.h>
#include <stdint.h>

// ---------------- problem constants ----------------
#define BB 2
#define SS 2048
#define DD 1024
#define HH 16
#define HD 64
#define LL 8
#define VV 32000
#define MM (BB*SS)          // 4096 rows
#define QKVS (3*DD)
#define FFS  (2*DD)

// ---------------- weight plane offsets ----------------
#define WMAT (DD*DD)
#define QKV_OFF 0                       // layer stride 3*WMAT (q,k,v row-blocks)
#define WO_OFF  (3*LL*WMAT)
#define W13_OFF (4*LL*WMAT)             // layer stride 2*WMAT (w1, w3 row-blocks)
#define W2_OFF  (6*LL*WMAT)
#define WOUT_OFF (7*LL*WMAT)
#define WTOT (WOUT_OFF + VV*DD)

// ---------------- scratch (device globals) ----------
__device__ float g_x[MM*DD];
__device__ __nv_bfloat16 g_whi[WTOT];
__device__ __nv_bfloat16 g_wlo[WTOT];
__device__ __nv_bfloat16 g_ahi[MM*DD];
__device__ __nv_bfloat16 g_alo[MM*DD];
__device__ __nv_bfloat16 g_qkvh[MM*QKVS];
__device__ __nv_bfloat16 g_qkvl[MM*QKVS];
__device__ __nv_bfloat16 g_ffh[MM*FFS];
__device__ __nv_bfloat16 g_ffl[MM*FFS];

// ================= helpers =================
__device__ __forceinline__ uint32_t smem_u32(const void* p) {
    uint32_t a;
    asm("{ .reg .u64 t; cvta.to.shared.u64 t, %1; cvt.u32.u64 %0, t; }"
        : "=r"(a) : "l"(p));
    return a;
}
#define CP16(dst, src) \
    asm volatile("cp.async.cg.shared.global [%0], [%1], 16;" :: "r"(dst), "l"(src))
#define CP_COMMIT() asm volatile("cp.async.commit_group;" ::: "memory")
#define CP_WAIT1()  asm volatile("cp.async.wait_group 1;" ::: "memory")
#define CP_WAIT0()  asm volatile("cp.async.wait_group 0;" ::: "memory")
#define LDSM4(r, addr) \
    asm volatile("ldmatrix.sync.aligned.m8n8.x4.shared.b16 {%0,%1,%2,%3}, [%4];" \
        : "=r"((r)[0]), "=r"((r)[1]), "=r"((r)[2]), "=r"((r)[3]) : "r"(addr))
#define MMA16816(c, a, b0v, b1v) \
    asm volatile("mma.sync.aligned.m16n8k16.row.col.f32.bf16.bf16.f32 " \
        "{%0,%1,%2,%3}, {%4,%5,%6,%7}, {%8,%9}, {%0,%1,%2,%3};" \
        : "+f"((c)[0]), "+f"((c)[1]), "+f"((c)[2]), "+f"((c)[3]) \
        : "r"((a)[0]), "r"((a)[1]), "r"((a)[2]), "r"((a)[3]), "r"(b0v), "r"(b1v))

__device__ __forceinline__ void split1(float x, __nv_bfloat16& h, __nv_bfloat16& l) {
    h = __float2bfloat16(x);
    l = __float2bfloat16(x - __bfloat162float(h));
}

// ---------------- fp32 -> (hi, lo) bf16 split (weights) ----------------
__global__ void conv_split(const float* __restrict__ src,
                           __nv_bfloat16* __restrict__ hi,
                           __nv_bfloat16* __restrict__ lo, int n4) {
    int i = blockIdx.x * 256 + threadIdx.x;
    if (i >= n4) return;
    float4 v = ((const float4*)src)[i];
    __nv_bfloat16 h0, h1, h2, h3, l0, l1, l2, l3;
    split1(v.x, h0, l0); split1(v.y, h1, l1);
    split1(v.z, h2, l2); split1(v.w, h3, l3);
    ((ushort4*)hi)[i] = make_ushort4(__bfloat16_as_ushort(h0), __bfloat16_as_ushort(h1),
                                     __bfloat16_as_ushort(h2), __bfloat16_as_ushort(h3));
    ((ushort4*)lo)[i] = make_ushort4(__bfloat16_as_ushort(l0), __bfloat16_as_ushort(l1),
                                     __bfloat16_as_ushort(l2), __bfloat16_as_ushort(l3));
}

// ================= mma.sync split-bf16 GEMM (R6-proven config) =============
// C[M,N] = A[M,K] @ W[N,K]^T. 128x128 tile, BK=32, 256 thr (8 warps 4x2,
// warp tile 32x64), double buffered, occ 2.
#define PLANE_B 10240
#define STAGE_B (4*PLANE_B)
#define GSMEM   (2*STAGE_B)

template<bool RESID, bool SPLITOUT>
__global__ void __launch_bounds__(256, 2)
gemm_mma(const __nv_bfloat16* __restrict__ Ahi, const __nv_bfloat16* __restrict__ Alo,
         const __nv_bfloat16* __restrict__ Bhi, const __nv_bfloat16* __restrict__ Blo,
         const float* __restrict__ R, float* __restrict__ C,
         __nv_bfloat16* __restrict__ Chi, __nv_bfloat16* __restrict__ Clo,
         int N, int K) {
    extern __shared__ char sm_raw[];
    uint32_t sb = smem_u32(sm_raw);
    int tid = threadIdx.x, lane = tid & 31, wid = tid >> 5;
    int wm = wid & 3, wn = wid >> 2;
    int m0 = blockIdx.y * 128, n0 = blockIdx.x * 128;

    int prow = tid >> 1;
    int pc   = (tid & 1) * 2;
    const __nv_bfloat16* srcs[4] = {Ahi, Alo, Bhi, Blo};

    int nslab = K / 32;

    {   // prologue
        #pragma unroll
        for (int p = 0; p < 4; p++) {
            int rb = (p < 2) ? m0 : n0;
            const __nv_bfloat16* g = srcs[p] + (size_t)(rb + prow) * K + pc * 8;
            uint32_t d = sb + p * PLANE_B + prow * 80 + pc * 16;
            CP16(d, g);
            CP16(d + 16, g + 8);
        }
        CP_COMMIT();
    }

    float acc[2][8][4] = {};
    int gq = lane >> 3, rr = lane & 7;

    for (int s = 0; s < nslab; s++) {
        if (s + 1 < nslab) {
            uint32_t stb = sb + ((s + 1) & 1) * STAGE_B;
            int k0 = (s + 1) * 32;
            #pragma unroll
            for (int p = 0; p < 4; p++) {
                int rb = (p < 2) ? m0 : n0;
                const __nv_bfloat16* g = srcs[p] + (size_t)(rb + prow) * K + k0 + pc * 8;
                uint32_t d = stb + p * PLANE_B + prow * 80 + pc * 16;
                CP16(d, g);
                CP16(d + 16, g + 8);
            }
            CP_COMMIT();
            CP_WAIT1();
        } else {
            CP_WAIT0();
        }
        __syncthreads();

        uint32_t stb = sb + (s & 1) * STAGE_B;
        #pragma unroll
        for (int ks = 0; ks < 2; ks++) {
            uint32_t ah[2][4], al[2][4];
            #pragma unroll
            for (int mf = 0; mf < 2; mf++) {
                int row = wm * 32 + mf * 16 + (gq & 1) * 8 + rr;
                int col = ks * 16 + (gq >> 1) * 8;
                uint32_t a = stb + row * 80 + col * 2;
                LDSM4(ah[mf], a);
                LDSM4(al[mf], a + PLANE_B);
            }
            #pragma unroll
            for (int np = 0; np < 4; np++) {
                uint32_t bh[4], bl[4];
                int row = wn * 64 + np * 16 + (gq >> 1) * 8 + rr;
                int col = ks * 16 + (gq & 1) * 8;
                uint32_t a = stb + 2 * PLANE_B + row * 80 + col * 2;
                LDSM4(bh, a);
                LDSM4(bl, a + PLANE_B);
                #pragma unroll
                for (int mf = 0; mf < 2; mf++) {
                    MMA16816(acc[mf][np*2],   ah[mf], bh[0], bh[1]);
                    MMA16816(acc[mf][np*2],   al[mf], bh[0], bh[1]);
                    MMA16816(acc[mf][np*2],   ah[mf], bl[0], bl[1]);
                    MMA16816(acc[mf][np*2+1], ah[mf], bh[2], bh[3]);
                    MMA16816(acc[mf][np*2+1], al[mf], bh[2], bh[3]);
                    MMA16816(acc[mf][np*2+1], ah[mf], bl[2], bl[3]);
                }
            }
        }
        __syncthreads();
    }

    int rbase = m0 + wm * 32 + (lane >> 2);
    int cbase = n0 + wn * 64 + (lane & 3) * 2;
    #pragma unroll
    for (int mf = 0; mf < 2; mf++) {
        #pragma unroll
        for (int nf = 0; nf < 8; nf++) {
            int row = rbase + mf * 16;
            int col = cbase + nf * 8;
            float v0 = acc[mf][nf][0], v1 = acc[mf][nf][1];
            float v2 = acc[mf][nf][2], v3 = acc[mf][nf][3];
            size_t a0 = (size_t)row * N + col;
            size_t a1 = (size_t)(row + 8) * N + col;
            if (SPLITOUT) {
                __nv_bfloat16 h0,h1,h2,h3,L0,L1,L2,L3;
                split1(v0, h0, L0); split1(v1, h1, L1);
                split1(v2, h2, L2); split1(v3, h3, L3);
                *(__nv_bfloat162*)(Chi + a0) = __halves2bfloat162(h0, h1);
                *(__nv_bfloat162*)(Clo + a0) = __halves2bfloat162(L0, L1);
                *(__nv_bfloat162*)(Chi + a1) = __halves2bfloat162(h2, h3);
                *(__nv_bfloat162*)(Clo + a1) = __halves2bfloat162(L2, L3);
            } else {
                if (RESID) {
                    float2 r0 = *(const float2*)(R + a0);
                    float2 r1 = *(const float2*)(R + a1);
                    v0 += r0.x; v1 += r0.y; v2 += r1.x; v3 += r1.y;
                }
                *(float2*)(C + a0) = make_float2(v0, v1);
                *(float2*)(C + a1) = make_float2(v2, v3);
            }
        }
    }
}

// ================= mma.sync flash attention (split-bf16 plane inputs) =====
#define ALD 72
#define APLANE (64*ALD*2)
#define ASMEM  (6*APLANE)

__global__ void __launch_bounds__(128)
attn_mma(const __nv_bfloat16* __restrict__ Ph, const __nv_bfloat16* __restrict__ Pl,
         __nv_bfloat16* __restrict__ Ohi, __nv_bfloat16* __restrict__ Olo) {
    extern __shared__ char asmr[];
    uint32_t sb = smem_u32(asmr);
    const uint32_t QH = sb, QL = sb + APLANE, KH = sb + 2*APLANE,
                   KL = sb + 3*APLANE, VH = sb + 4*APLANE, VL = sb + 5*APLANE;

    int tid = threadIdx.x, lane = tid & 31, w = tid >> 5;
    int gq = lane >> 3, rr = lane & 7;
    int bh = blockIdx.y;
    int b = bh / HH, h = bh % HH;
    int qt = blockIdx.x;
    float slope = exp2f(-0.5f * (float)(h + 1));

    int lrow = tid >> 4;          // 0..7
    int lcol = (tid & 15) * 4;    // 0..60

    // ---- load Q tile (exact x0.125 scale on bf16 planes) ----
    __nv_bfloat162 sc2 = __float2bfloat162_rn(0.125f);
    #pragma unroll
    for (int pass = 0; pass < 8; pass++) {
        int row = lrow + pass * 8;
        size_t ga = (size_t)(b*SS + qt*64 + row) * QKVS + h*HD + lcol;
        uint2 qh2 = *(const uint2*)(Ph + ga);
        uint2 ql2 = *(const uint2*)(Pl + ga);
        __nv_bfloat162 a0 = __hmul2(*(__nv_bfloat162*)&qh2.x, sc2);
        __nv_bfloat162 a1 = __hmul2(*(__nv_bfloat162*)&qh2.y, sc2);
        __nv_bfloat162 b0 = __hmul2(*(__nv_bfloat162*)&ql2.x, sc2);
        __nv_bfloat162 b1 = __hmul2(*(__nv_bfloat162*)&ql2.y, sc2);
        uint32_t off = (row*ALD + lcol) * 2;
        *(uint2*)(asmr + (QH - sb) + off) = make_uint2(*(uint32_t*)&a0, *(uint32_t*)&a1);
        *(uint2*)(asmr + (QL - sb) + off) = make_uint2(*(uint32_t*)&b0, *(uint32_t*)&b1);
    }
    __syncthreads();

    uint32_t qh[4][4], ql[4][4];
    #pragma unroll
    for (int kk = 0; kk < 4; kk++) {
        uint32_t off = ((w*16 + (gq & 1)*8 + rr)*ALD + kk*16 + (gq >> 1)*8) * 2;
        LDSM4(qh[kk], QH + off);
        LDSM4(ql[kk], QL + off);
    }

    float m0r = -INFINITY, m1r = -INFINITY, l0s = 0.f, l1s = 0.f;
    float o[8][4] = {};
    int qg0 = qt*64 + w*16 + (lane >> 2);
    int qg1 = qg0 + 8;

    for (int kt = 0; kt <= qt; kt++) {
        __syncthreads();
        #pragma unroll
        for (int pass = 0; pass < 8; pass++) {
            int row = lrow + pass * 8;
            size_t gr = (size_t)(b*SS + kt*64 + row) * QKVS + h*HD + lcol;
            uint2 kh2 = *(const uint2*)(Ph + gr + DD);
            uint2 kl2 = *(const uint2*)(Pl + gr + DD);
            uint32_t off = (row*ALD + lcol) * 2;
            *(uint2*)(asmr + (KH - sb) + off) = kh2;
            *(uint2*)(asmr + (KL - sb) + off) = kl2;
            uint2 vh2 = *(const uint2*)(Ph + gr + 2*DD);
            uint2 vl2 = *(const uint2*)(Pl + gr + 2*DD);
            const __nv_bfloat16* vh = (const __nv_bfloat16*)&vh2;
            const __nv_bfloat16* vl = (const __nv_bfloat16*)&vl2;
            #pragma unroll
            for (int i = 0; i < 4; i++) {
                uint32_t toff = ((lcol + i)*ALD + row) * 2;
                *(__nv_bfloat16*)(asmr + (VH - sb) + toff) = vh[i];
                *(__nv_bfloat16*)(asmr + (VL - sb) + toff) = vl[i];
            }
        }
        __syncthreads();

        // ---- S = Q @ K^T ----
        float s[8][4] = {};
        #pragma unroll
        for (int kk = 0; kk < 4; kk++) {
            #pragma unroll
            for (int np = 0; np < 4; np++) {
                uint32_t kb[4], kl2[4];
                uint32_t off = ((np*16 + (gq >> 1)*8 + rr)*ALD + kk*16 + (gq & 1)*8) * 2;
                LDSM4(kb, KH + off);
                LDSM4(kl2, KL + off);
                MMA16816(s[np*2],   qh[kk], kb[0], kb[1]);
                MMA16816(s[np*2],   ql[kk], kb[0], kb[1]);
                MMA16816(s[np*2],   qh[kk], kl2[0], kl2[1]);
                MMA16816(s[np*2+1], qh[kk], kb[2], kb[3]);
                MMA16816(s[np*2+1], ql[kk], kb[2], kb[3]);
                MMA16816(s[np*2+1], qh[kk], kl2[2], kl2[3]);
            }
        }

        // ---- ALiBi bias + causal mask ----
        #pragma unroll
        for (int nf = 0; nf < 8; nf++) {
            #pragma unroll
            for (int c = 0; c < 2; c++) {
                int kg = kt*64 + nf*8 + (lane & 3)*2 + c;
                s[nf][c]   = (kg <= qg0) ? s[nf][c]   + slope*(float)(kg - qg0) : -1e30f;
                s[nf][2+c] = (kg <= qg1) ? s[nf][2+c] + slope*(float)(kg - qg1) : -1e30f;
            }
        }

        // ---- online softmax ----
        float mx0 = -1e30f, mx1 = -1e30f;
        #pragma unroll
        for (int nf = 0; nf < 8; nf++) {
            mx0 = fmaxf(mx0, fmaxf(s[nf][0], s[nf][1]));
            mx1 = fmaxf(mx1, fmaxf(s[nf][2], s[nf][3]));
        }
        #pragma unroll
        for (int off = 1; off <= 2; off <<= 1) {
            mx0 = fmaxf(mx0, __shfl_xor_sync(0xffffffffu, mx0, off));
            mx1 = fmaxf(mx1, __shfl_xor_sync(0xffffffffu, mx1, off));
        }
        float mn0 = fmaxf(m0r, mx0), mn1 = fmaxf(m1r, mx1);
        float al0 = __expf(m0r - mn0), al1 = __expf(m1r - mn1);
        float rs0 = 0.f, rs1 = 0.f;
        #pragma unroll
        for (int nf = 0; nf < 8; nf++) {
            s[nf][0] = __expf(s[nf][0] - mn0);
            s[nf][1] = __expf(s[nf][1] - mn0);
            s[nf][2] = __expf(s[nf][2] - mn1);
            s[nf][3] = __expf(s[nf][3] - mn1);
            rs0 += s[nf][0] + s[nf][1];
            rs1 += s[nf][2] + s[nf][3];
        }
        #pragma unroll
        for (int off = 1; off <= 2; off <<= 1) {
            rs0 += __shfl_xor_sync(0xffffffffu, rs0, off);
            rs1 += __shfl_xor_sync(0xffffffffu, rs1, off);
        }
        l0s = l0s * al0 + rs0;
        l1s = l1s * al1 + rs1;
        m0r = mn0; m1r = mn1;

        #pragma unroll
        for (int nf = 0; nf < 8; nf++) {
            o[nf][0] *= al0; o[nf][1] *= al0;
            o[nf][2] *= al1; o[nf][3] *= al1;
        }

        // ---- O += P @ V (P split on the fly) ----
        #pragma unroll
        for (int kk = 0; kk < 4; kk++) {
            uint32_t Ah[4], Al2[4];
            #pragma unroll
            for (int half = 0; half < 2; half++) {
                float* sv = s[2*kk + half];
                __nv_bfloat162 h01 = __floats2bfloat162_rn(sv[0], sv[1]);
                __nv_bfloat162 h23 = __floats2bfloat162_rn(sv[2], sv[3]);
                __nv_bfloat162 L01 = __floats2bfloat162_rn(
                    sv[0] - __bfloat162float(__low2bfloat16(h01)),
                    sv[1] - __bfloat162float(__high2bfloat16(h01)));
                __nv_bfloat162 L23 = __floats2bfloat162_rn(
                    sv[2] - __bfloat162float(__low2bfloat16(h23)),
                    sv[3] - __bfloat162float(__high2bfloat16(h23)));
                Ah[half*2 + 0] = *(uint32_t*)&h01;
                Ah[half*2 + 1] = *(uint32_t*)&h23;
                Al2[half*2 + 0] = *(uint32_t*)&L01;
                Al2[half*2 + 1] = *(uint32_t*)&L23;
            }
            #pragma unroll
            for (int np = 0; np < 4; np++) {
                uint32_t vb[4], vl2[4];
                uint32_t off = ((np*16 + (gq >> 1)*8 + rr)*ALD + kk*16 + (gq & 1)*8) * 2;
                LDSM4(vb, VH + off);
                LDSM4(vl2, VL + off);
                MMA16816(o[np*2],   Ah,  vb[0], vb[1]);
                MMA16816(o[np*2],   Al2, vb[0], vb[1]);
                MMA16816(o[np*2],   Ah,  vl2[0], vl2[1]);
                MMA16816(o[np*2+1], Ah,  vb[2], vb[3]);
                MMA16816(o[np*2+1], Al2, vb[2], vb[3]);
                MMA16816(o[np*2+1], Ah,  vl2[2], vl2[3]);
            }
        }
    }

    // ---- epilogue ----
    float inv0 = 1.f / l0s, inv1 = 1.f / l1s;
    int row0 = b*SS + qt*64 + w*16 + (lane >> 2);
    int colb = h*HD + (lane & 3)*2;
    #pragma unroll
    for (int nf = 0; nf < 8; nf++) {
        float v0 = o[nf][0]*inv0, v1 = o[nf][1]*inv0;
        float v2 = o[nf][2]*inv1, v3 = o[nf][3]*inv1;
        size_t a0 = (size_t)row0 * DD + colb + nf*8;
        size_t a1 = (size_t)(row0 + 8) * DD + colb + nf*8;
        __nv_bfloat16 h0,h1,h2,h3,L0,L1,L2,L3;
        split1(v0, h0, L0); split1(v1, h1, L1);
        split1(v2, h2, L2); split1(v3, h3, L3);
        *(__nv_bfloat162*)(Ohi + a0) = __halves2bfloat162(h0, h1);
        *(__nv_bfloat162*)(Olo + a0) = __halves2bfloat162(L0, L1);
        *(__nv_bfloat162*)(Ohi + a1) = __halves2bfloat162(h2, h3);
        *(__nv_bfloat162*)(Olo + a1) = __halves2bfloat162(L2, L3);
    }
}

// ---------------- embedding lookup ----------------
__global__ void embed_kernel(const int* __restrict__ tokens,
                             const float* __restrict__ emb,
                             float* __restrict__ x) {
    int row = blockIdx.x;
    int tok = tokens[row];
    const float4* src = (const float4*)(emb + (size_t)tok * DD);
    float4* dst = (float4*)(x + (size_t)row * DD);
    for (int i = threadIdx.x; i < DD/4; i += blockDim.x) dst[i] = src[i];
}

// ---------------- layernorm -> bf16 hi/lo planes ----------------
__global__ void ln_kernel(const float* __restrict__ x,
                          const float* __restrict__ gw,
                          const float* __restrict__ bw,
                          __nv_bfloat16* __restrict__ hi,
                          __nv_bfloat16* __restrict__ lo) {
    int row = blockIdx.x;
    const float* xr = x + (size_t)row * DD;
    float s = 0.f, s2 = 0.f;
    for (int i = threadIdx.x; i < DD; i += 256) {
        float v = xr[i];
        s += v;
        s2 = fmaf(v, v, s2);
    }
    __shared__ float rs[8], rs2[8];
    #pragma unroll
    for (int o = 16; o > 0; o >>= 1) {
        s  += __shfl_down_sync(0xffffffffu, s,  o);
        s2 += __shfl_down_sync(0xffffffffu, s2, o);
    }
    int w = threadIdx.x >> 5;
    if ((threadIdx.x & 31) == 0) { rs[w] = s; rs2[w] = s2; }
    __syncthreads();
    __shared__ float mean_s, rstd_s;
    if (threadIdx.x == 0) {
        float ts = 0.f, ts2 = 0.f;
        #pragma unroll
        for (int i = 0; i < 8; i++) { ts += rs[i]; ts2 += rs2[i]; }
        float m = ts / (float)DD;
        float var = ts2 / (float)DD - m * m;
        mean_s = m;
        rstd_s = rsqrtf(var + 1e-5f);
    }
    __syncthreads();
    float m = mean_s, r = rstd_s;
    __nv_bfloat16* hrow = hi + (size_t)row * DD;
    __nv_bfloat16* lrow = lo + (size_t)row * DD;
    for (int i = threadIdx.x; i < DD; i += 256) {
        float v = (xr[i] - m) * r * gw[i] + bw[i];
        __nv_bfloat16 vh, vl;
        split1(v, vh, vl);
        hrow[i] = vh;
        lrow[i] = vl;
    }
}

// ---------------- SwiGLU from packed ff planes -> bf16 hi/lo --------------
__global__ void swiglu_kernel(const __nv_bfloat16* __restrict__ fh,
                              const __nv_bfloat16* __restrict__ fl,
                              __nv_bfloat16* __restrict__ hi,
                              __nv_bfloat16* __restrict__ lo) {
    int i = blockIdx.x * 256 + threadIdx.x;   // over MM*DD/4 quads
    int row = i / (DD/4);
    int c4 = (i % (DD/4)) * 4;
    size_t fa = (size_t)row * FFS + c4;
    ushort4 ah4 = *(const ushort4*)(fh + fa);
    ushort4 al4 = *(const ushort4*)(fl + fa);
    ushort4 ch4 = *(const ushort4*)(fh + fa + DD);
    ushort4 cl4 = *(const ushort4*)(fl + fa + DD);
    float x0 = __bfloat162float(__ushort_as_bfloat16(ah4.x)) + __bfloat162float(__ushort_as_bfloat16(al4.x));
    float x1 = __bfloat162float(__ushort_as_bfloat16(ah4.y)) + __bfloat162float(__ushort_as_bfloat16(al4.y));
    float x2 = __bfloat162float(__ushort_as_bfloat16(ah4.z)) + __bfloat162float(__ushort_as_bfloat16(al4.z));
    float x3 = __bfloat162float(__ushort_as_bfloat16(ah4.w)) + __bfloat162float(__ushort_as_bfloat16(al4.w));
    float c0 = __bfloat162float(__ushort_as_bfloat16(ch4.x)) + __bfloat162float(__ushort_as_bfloat16(cl4.x));
    float c1 = __bfloat162float(__ushort_as_bfloat16(ch4.y)) + __bfloat162float(__ushort_as_bfloat16(cl4.y));
    float c2 = __bfloat162float(__ushort_as_bfloat16(ch4.z)) + __bfloat162float(__ushort_as_bfloat16(cl4.z));
    float c3 = __bfloat162float(__ushort_as_bfloat16(ch4.w)) + __bfloat162float(__ushort_as_bfloat16(cl4.w));
    float r0 = x0 / (1.f + __expf(-x0)) * c0;
    float r1 = x1 / (1.f + __expf(-x1)) * c1;
    float r2 = x2 / (1.f + __expf(-x2)) * c2;
    float r3 = x3 / (1.f + __expf(-x3)) * c3;
    __nv_bfloat16 h0,h1,h2,h3,l0,l1,l2,l3;
    split1(r0, h0, l0); split1(r1, h1, l1);
    split1(r2, h2, l2); split1(r3, h3, l3);
    size_t oa = (size_t)row * DD + c4;
    *(ushort4*)(hi + oa) = make_ushort4(__bfloat16_as_ushort(h0), __bfloat16_as_ushort(h1),
                                        __bfloat16_as_ushort(h2), __bfloat16_as_ushort(h3));
    *(ushort4*)(lo + oa) = make_ushort4(__bfloat16_as_ushort(l0), __bfloat16_as_ushort(l1),
                                        __bfloat16_as_ushort(l2), __bfloat16_as_ushort(l3));
}

// ---------------- launch ----------------
extern "C" void kernel_launch(void* const* d_in, const int* in_sizes, int n_in,
                              void* d_out, int out_size) {
    const int*   tokens = (const int*)d_in[0];
    const float* emb    = (const float*)d_in[1];
    const float* wq     = (const float*)d_in[2];
    const float* wk     = (const float*)d_in[3];
    const float* wv     = (const float*)d_in[4];
    const float* wo     = (const float*)d_in[5];
    const float* ln1_g  = (const float*)d_in[6];
    const float* ln1_b  = (const float*)d_in[7];
    const float* ln2_g  = (const float*)d_in[8];
    const float* ln2_b  = (const float*)d_in[9];
    const float* w1     = (const float*)d_in[10];
    const float* w2     = (const float*)d_in[11];
    const float* w3     = (const float*)d_in[12];
    const float* lnf_g  = (const float*)d_in[13];
    const float* lnf_b  = (const float*)d_in[14];
    const float* w_out  = (const float*)d_in[15];
    float* out = (float*)d_out;

    float* px;
    cudaGetSymbolAddress((void**)&px, g_x);
    __nv_bfloat16 *whi, *wlo, *ahi, *alo, *qkvh, *qkvl, *ffh, *ffl;
    cudaGetSymbolAddress((void**)&whi, g_whi);
    cudaGetSymbolAddress((void**)&wlo, g_wlo);
    cudaGetSymbolAddress((void**)&ahi, g_ahi);
    cudaGetSymbolAddress((void**)&alo, g_alo);
    cudaGetSymbolAddress((void**)&qkvh, g_qkvh);
    cudaGetSymbolAddress((void**)&qkvl, g_qkvl);
    cudaGetSymbolAddress((void**)&ffh, g_ffh);
    cudaGetSymbolAddress((void**)&ffl, g_ffl);

    cudaFuncSetAttribute(attn_mma,
                         cudaFuncAttributeMaxDynamicSharedMemorySize, ASMEM);
    cudaFuncSetAttribute(gemm_mma<false,true>,
                         cudaFuncAttributeMaxDynamicSharedMemorySize, GSMEM);
    cudaFuncSetAttribute(gemm_mma<true,false>,
                         cudaFuncAttributeMaxDynamicSharedMemorySize, GSMEM);
    cudaFuncSetAttribute(gemm_mma<false,false>,
                         cudaFuncAttributeMaxDynamicSharedMemorySize, GSMEM);

    // ---- convert weights to bf16 hi/lo planes (packed layouts) ----
    {
        int n4 = WMAT / 4;
        for (int l = 0; l < LL; l++) {
            size_t so = (size_t)l * WMAT;
            size_t qo = QKV_OFF + (size_t)l * 3 * WMAT;
            conv_split<<<n4/256, 256>>>(wq + so, whi + qo,          wlo + qo,          n4);
            conv_split<<<n4/256, 256>>>(wk + so, whi + qo + WMAT,   wlo + qo + WMAT,   n4);
            conv_split<<<n4/256, 256>>>(wv + so, whi + qo + 2*WMAT, wlo + qo + 2*WMAT, n4);
            size_t fo = W13_OFF + (size_t)l * 2 * WMAT;
            conv_split<<<n4/256, 256>>>(w1 + so, whi + fo,          wlo + fo,          n4);
            conv_split<<<n4/256, 256>>>(w3 + so, whi + fo + WMAT,   wlo + fo + WMAT,   n4);
        }
        int n4L = (LL * WMAT) / 4;
        conv_split<<<n4L/256, 256>>>(wo, whi + WO_OFF, wlo + WO_OFF, n4L);
        conv_split<<<n4L/256, 256>>>(w2, whi + W2_OFF, wlo + W2_OFF, n4L);
        int n4o = (VV * DD) / 4;
        conv_split<<<n4o/256, 256>>>(w_out, whi + WOUT_OFF, wlo + WOUT_OFF, n4o);
    }

    embed_kernel<<<MM, 256>>>(tokens, emb, px);

    dim3 gQKV(QKVS/128, MM/128);
    dim3 gD(DD/128, MM/128);
    dim3 gFF(FFS/128, MM/128);
    for (int l = 0; l < LL; l++) {
        size_t qo = QKV_OFF + (size_t)l * 3 * WMAT;
        size_t oo = WO_OFF + (size_t)l * WMAT;
        size_t fo = W13_OFF + (size_t)l * 2 * WMAT;
        size_t to = W2_OFF + (size_t)l * WMAT;

        // attention
        ln_kernel<<<MM, 256>>>(px, ln1_g + l*DD, ln1_b + l*DD, ahi, alo);
        gemm_mma<false,true><<<gQKV, 256, GSMEM>>>(ahi, alo, whi + qo, wlo + qo,
                                                   nullptr, nullptr, qkvh, qkvl, QKVS, DD);
        attn_mma<<<dim3(SS/64, BB*HH), 128, ASMEM>>>(qkvh, qkvl, ahi, alo);
        gemm_mma<true,false><<<gD, 256, GSMEM>>>(ahi, alo, whi + oo, wlo + oo,
                                                 px, px, nullptr, nullptr, DD, DD);

        // SwiGLU FFN
        ln_kernel<<<MM, 256>>>(px, ln2_g + l*DD, ln2_b + l*DD, ahi, alo);
        gemm_mma<false,true><<<gFF, 256, GSMEM>>>(ahi, alo, whi + fo, wlo + fo,
                                                  nullptr, nullptr, ffh, ffl, FFS, DD);
        swiglu_kernel<<<(MM*DD/4)/256, 256>>>(ffh, ffl, ahi, alo);
        gemm_mma<true,false><<<gD, 256, GSMEM>>>(ahi, alo, whi + to, wlo + to,
                                                 px, px, nullptr, nullptr, DD, DD);
    }

    // final LN + logits
    ln_kernel<<<MM, 256>>>(px, lnf_g, lnf_b, ahi, alo);
    gemm_mma<false,false><<<dim3(VV/128, MM/128), 256, GSMEM>>>(
        ahi, alo, whi + WOUT_OFF, wlo + WOUT_OFF, nullptr, out, nullptr, nullptr, VV, DD);
}

// round 11
// speedup vs baseline: 1.2803x; 1.1163x over previous
#include <cuda_runtime.h>
#include <cuda_bf16.h>
#include <math.h>
#include <stdint.h>

// ---------------- problem constants ----------------
#define BB 2
#define SS 2048
#define DD 1024
#define HH 16
#define HD 64
#define LL 8
#define VV 32000
#define MM (BB*SS)          // 4096 rows
#define QKVS (3*DD)
#define FFS  (2*DD)

// ---------------- weight plane offsets ----------------
#define WMAT (DD*DD)
#define QKV_OFF 0                       // layer stride 3*WMAT (q,k,v row-blocks)
#define WO_OFF  (3*LL*WMAT)
#define W13_OFF (4*LL*WMAT)             // layer stride 2*WMAT (w1, w3 row-blocks)
#define W2_OFF  (6*LL*WMAT)
#define WOUT_OFF (7*LL*WMAT)
#define WTOT (WOUT_OFF + VV*DD)

// ---------------- scratch (device globals) ----------
__device__ float g_x[MM*DD];
__device__ __nv_bfloat16 g_whi[WTOT];
__device__ __nv_bfloat16 g_wlo[WTOT];
__device__ __nv_bfloat16 g_ahi[MM*DD];
__device__ __nv_bfloat16 g_alo[MM*DD];
__device__ __nv_bfloat16 g_qkvh[MM*QKVS];
__device__ __nv_bfloat16 g_qkvl[MM*QKVS];
__device__ __nv_bfloat16 g_ffh[MM*FFS];
__device__ __nv_bfloat16 g_ffl[MM*FFS];

// ================= helpers =================
__device__ __forceinline__ uint32_t smem_u32(const void* p) {
    uint32_t a;
    asm("{ .reg .u64 t; cvta.to.shared.u64 t, %1; cvt.u32.u64 %0, t; }"
        : "=r"(a) : "l"(p));
    return a;
}
#define CP16(dst, src) \
    asm volatile("cp.async.cg.shared.global [%0], [%1], 16;" :: "r"(dst), "l"(src))
#define CP8(dst, src) \
    asm volatile("cp.async.ca.shared.global [%0], [%1], 8;" :: "r"(dst), "l"(src))
#define CP_COMMIT() asm volatile("cp.async.commit_group;" ::: "memory")
#define CP_WAIT1()  asm volatile("cp.async.wait_group 1;" ::: "memory")
#define CP_WAIT0()  asm volatile("cp.async.wait_group 0;" ::: "memory")
#define LDSM4(r, addr) \
    asm volatile("ldmatrix.sync.aligned.m8n8.x4.shared.b16 {%0,%1,%2,%3}, [%4];" \
        : "=r"((r)[0]), "=r"((r)[1]), "=r"((r)[2]), "=r"((r)[3]) : "r"(addr))
#define LDSM4T(r, addr) \
    asm volatile("ldmatrix.sync.aligned.m8n8.x4.trans.shared.b16 {%0,%1,%2,%3}, [%4];" \
        : "=r"((r)[0]), "=r"((r)[1]), "=r"((r)[2]), "=r"((r)[3]) : "r"(addr))
#define MMA16816(c, a, b0v, b1v) \
    asm volatile("mma.sync.aligned.m16n8k16.row.col.f32.bf16.bf16.f32 " \
        "{%0,%1,%2,%3}, {%4,%5,%6,%7}, {%8,%9}, {%0,%1,%2,%3};" \
        : "+f"((c)[0]), "+f"((c)[1]), "+f"((c)[2]), "+f"((c)[3]) \
        : "r"((a)[0]), "r"((a)[1]), "r"((a)[2]), "r"((a)[3]), "r"(b0v), "r"(b1v))

__device__ __forceinline__ void split1(float x, __nv_bfloat16& h, __nv_bfloat16& l) {
    h = __float2bfloat16(x);
    l = __float2bfloat16(x - __bfloat162float(h));
}

// ---------------- fp32 -> (hi, lo) bf16 split (weights) ----------------
__global__ void conv_split(const float* __restrict__ src,
                           __nv_bfloat16* __restrict__ hi,
                           __nv_bfloat16* __restrict__ lo, int n4) {
    int i = blockIdx.x * 256 + threadIdx.x;
    if (i >= n4) return;
    float4 v = ((const float4*)src)[i];
    __nv_bfloat16 h0, h1, h2, h3, l0, l1, l2, l3;
    split1(v.x, h0, l0); split1(v.y, h1, l1);
    split1(v.z, h2, l2); split1(v.w, h3, l3);
    ((ushort4*)hi)[i] = make_ushort4(__bfloat16_as_ushort(h0), __bfloat16_as_ushort(h1),
                                     __bfloat16_as_ushort(h2), __bfloat16_as_ushort(h3));
    ((ushort4*)lo)[i] = make_ushort4(__bfloat16_as_ushort(l0), __bfloat16_as_ushort(l1),
                                     __bfloat16_as_ushort(l2), __bfloat16_as_ushort(l3));
}

// ================= mma.sync split-bf16 GEMM (R6-proven config) =============
// C[M,N] = A[M,K] @ W[N,K]^T. 128x128 tile, BK=32, 256 thr (8 warps 4x2,
// warp tile 32x64), double buffered, occ 2.
#define PLANE_B 10240
#define STAGE_B (4*PLANE_B)
#define GSMEM   (2*STAGE_B)

template<bool RESID, bool SPLITOUT>
__global__ void __launch_bounds__(256, 2)
gemm_mma(const __nv_bfloat16* __restrict__ Ahi, const __nv_bfloat16* __restrict__ Alo,
         const __nv_bfloat16* __restrict__ Bhi, const __nv_bfloat16* __restrict__ Blo,
         const float* __restrict__ R, float* __restrict__ C,
         __nv_bfloat16* __restrict__ Chi, __nv_bfloat16* __restrict__ Clo,
         int N, int K) {
    extern __shared__ char sm_raw[];
    uint32_t sb = smem_u32(sm_raw);
    int tid = threadIdx.x, lane = tid & 31, wid = tid >> 5;
    int wm = wid & 3, wn = wid >> 2;
    int m0 = blockIdx.y * 128, n0 = blockIdx.x * 128;

    int prow = tid >> 1;
    int pc   = (tid & 1) * 2;
    const __nv_bfloat16* srcs[4] = {Ahi, Alo, Bhi, Blo};
    int nslab = K / 32;

    {
        #pragma unroll
        for (int p = 0; p < 4; p++) {
            int rb = (p < 2) ? m0 : n0;
            const __nv_bfloat16* g = srcs[p] + (size_t)(rb + prow) * K + pc * 8;
            uint32_t d = sb + p * PLANE_B + prow * 80 + pc * 16;
            CP16(d, g);
            CP16(d + 16, g + 8);
        }
        CP_COMMIT();
    }

    float acc[2][8][4] = {};
    int gq = lane >> 3, rr = lane & 7;

    for (int s = 0; s < nslab; s++) {
        if (s + 1 < nslab) {
            uint32_t stb = sb + ((s + 1) & 1) * STAGE_B;
            int k0 = (s + 1) * 32;
            #pragma unroll
            for (int p = 0; p < 4; p++) {
                int rb = (p < 2) ? m0 : n0;
                const __nv_bfloat16* g = srcs[p] + (size_t)(rb + prow) * K + k0 + pc * 8;
                uint32_t d = stb + p * PLANE_B + prow * 80 + pc * 16;
                CP16(d, g);
                CP16(d + 16, g + 8);
            }
            CP_COMMIT();
            CP_WAIT1();
        } else {
            CP_WAIT0();
        }
        __syncthreads();

        uint32_t stb = sb + (s & 1) * STAGE_B;
        #pragma unroll
        for (int ks = 0; ks < 2; ks++) {
            uint32_t ah[2][4], al[2][4];
            #pragma unroll
            for (int mf = 0; mf < 2; mf++) {
                int row = wm * 32 + mf * 16 + (gq & 1) * 8 + rr;
                int col = ks * 16 + (gq >> 1) * 8;
                uint32_t a = stb + row * 80 + col * 2;
                LDSM4(ah[mf], a);
                LDSM4(al[mf], a + PLANE_B);
            }
            #pragma unroll
            for (int np = 0; np < 4; np++) {
                uint32_t bh[4], bl[4];
                int row = wn * 64 + np * 16 + (gq >> 1) * 8 + rr;
                int col = ks * 16 + (gq & 1) * 8;
                uint32_t a = stb + 2 * PLANE_B + row * 80 + col * 2;
                LDSM4(bh, a);
                LDSM4(bl, a + PLANE_B);
                #pragma unroll
                for (int mf = 0; mf < 2; mf++) {
                    MMA16816(acc[mf][np*2],   ah[mf], bh[0], bh[1]);
                    MMA16816(acc[mf][np*2],   al[mf], bh[0], bh[1]);
                    MMA16816(acc[mf][np*2],   ah[mf], bl[0], bl[1]);
                    MMA16816(acc[mf][np*2+1], ah[mf], bh[2], bh[3]);
                    MMA16816(acc[mf][np*2+1], al[mf], bh[2], bh[3]);
                    MMA16816(acc[mf][np*2+1], ah[mf], bl[2], bl[3]);
                }
            }
        }
        __syncthreads();
    }

    int rbase = m0 + wm * 32 + (lane >> 2);
    int cbase = n0 + wn * 64 + (lane & 3) * 2;
    #pragma unroll
    for (int mf = 0; mf < 2; mf++) {
        #pragma unroll
        for (int nf = 0; nf < 8; nf++) {
            int row = rbase + mf * 16;
            int col = cbase + nf * 8;
            float v0 = acc[mf][nf][0], v1 = acc[mf][nf][1];
            float v2 = acc[mf][nf][2], v3 = acc[mf][nf][3];
            size_t a0 = (size_t)row * N + col;
            size_t a1 = (size_t)(row + 8) * N + col;
            if (SPLITOUT) {
                __nv_bfloat16 h0,h1,h2,h3,L0,L1,L2,L3;
                split1(v0, h0, L0); split1(v1, h1, L1);
                split1(v2, h2, L2); split1(v3, h3, L3);
                *(__nv_bfloat162*)(Chi + a0) = __halves2bfloat162(h0, h1);
                *(__nv_bfloat162*)(Clo + a0) = __halves2bfloat162(L0, L1);
                *(__nv_bfloat162*)(Chi + a1) = __halves2bfloat162(h2, h3);
                *(__nv_bfloat162*)(Clo + a1) = __halves2bfloat162(L2, L3);
            } else {
                if (RESID) {
                    float2 r0 = *(const float2*)(R + a0);
                    float2 r1 = *(const float2*)(R + a1);
                    v0 += r0.x; v1 += r0.y; v2 += r1.x; v3 += r1.y;
                }
                *(float2*)(C + a0) = make_float2(v0, v1);
                *(float2*)(C + a1) = make_float2(v2, v3);
            }
        }
    }
}

// ================= mma.sync flash attention =================
// V stored ROW-MAJOR [key][hd]; PV B-frags via ldmatrix.trans.
// All smem fills are verbatim 8B cp.async; Q scale 0.125 applied in epilogue.
#define ALD 72
#define APLANE (64*ALD*2)
#define ASMEM  (6*APLANE)

__global__ void __launch_bounds__(128)
attn_mma(const __nv_bfloat16* __restrict__ Ph, const __nv_bfloat16* __restrict__ Pl,
         __nv_bfloat16* __restrict__ Ohi, __nv_bfloat16* __restrict__ Olo) {
    extern __shared__ char asmr[];
    uint32_t sb = smem_u32(asmr);
    const uint32_t QH = sb, QL = sb + APLANE, KH = sb + 2*APLANE,
                   KL = sb + 3*APLANE, VH = sb + 4*APLANE, VL = sb + 5*APLANE;

    int tid = threadIdx.x, lane = tid & 31, w = tid >> 5;
    int gq = lane >> 3, rr = lane & 7;
    int bh = blockIdx.y;
    int b = bh / HH, h = bh % HH;
    int qt = blockIdx.x;
    float slope = exp2f(-0.5f * (float)(h + 1));

    int lrow = tid >> 4;          // 0..7
    int lcol = (tid & 15) * 4;    // 0..60

    // ---- Q tile: verbatim 8B async copies ----
    #pragma unroll
    for (int pass = 0; pass < 8; pass++) {
        int row = lrow + pass * 8;
        size_t ga = (size_t)(b*SS + qt*64 + row) * QKVS + h*HD + lcol;
        uint32_t off = (row*ALD + lcol) * 2;
        CP8(QH + off, Ph + ga);
        CP8(QL + off, Pl + ga);
    }
    CP_COMMIT();
    CP_WAIT0();
    __syncthreads();

    uint32_t qh[4][4], ql[4][4];
    #pragma unroll
    for (int kk = 0; kk < 4; kk++) {
        uint32_t off = ((w*16 + (gq & 1)*8 + rr)*ALD + kk*16 + (gq >> 1)*8) * 2;
        LDSM4(qh[kk], QH + off);
        LDSM4(ql[kk], QL + off);
    }

    float m0r = -INFINITY, m1r = -INFINITY, l0s = 0.f, l1s = 0.f;
    float o[8][4] = {};
    int qg0 = qt*64 + w*16 + (lane >> 2);
    int qg1 = qg0 + 8;

    for (int kt = 0; kt <= qt; kt++) {
        __syncthreads();
        // K and V (row-major) planes, verbatim 8B async copies
        #pragma unroll
        for (int pass = 0; pass < 8; pass++) {
            int row = lrow + pass * 8;
            size_t gr = (size_t)(b*SS + kt*64 + row) * QKVS + h*HD + lcol;
            uint32_t off = (row*ALD + lcol) * 2;
            CP8(KH + off, Ph + gr + DD);
            CP8(KL + off, Pl + gr + DD);
            CP8(VH + off, Ph + gr + 2*DD);
            CP8(VL + off, Pl + gr + 2*DD);
        }
        CP_COMMIT();
        CP_WAIT0();
        __syncthreads();

        // ---- S = Q @ K^T (unscaled) ----
        float s[8][4] = {};
        #pragma unroll
        for (int kk = 0; kk < 4; kk++) {
            #pragma unroll
            for (int np = 0; np < 4; np++) {
                uint32_t kb[4], kl2[4];
                uint32_t off = ((np*16 + (gq >> 1)*8 + rr)*ALD + kk*16 + (gq & 1)*8) * 2;
                LDSM4(kb, KH + off);
                LDSM4(kl2, KL + off);
                MMA16816(s[np*2],   qh[kk], kb[0], kb[1]);
                MMA16816(s[np*2],   ql[kk], kb[0], kb[1]);
                MMA16816(s[np*2],   qh[kk], kl2[0], kl2[1]);
                MMA16816(s[np*2+1], qh[kk], kb[2], kb[3]);
                MMA16816(s[np*2+1], ql[kk], kb[2], kb[3]);
                MMA16816(s[np*2+1], qh[kk], kl2[2], kl2[3]);
            }
        }

        // ---- scale (1/sqrt(64)) + ALiBi bias + causal mask ----
        #pragma unroll
        for (int nf = 0; nf < 8; nf++) {
            #pragma unroll
            for (int c = 0; c < 2; c++) {
                int kg = kt*64 + nf*8 + (lane & 3)*2 + c;
                float sv0 = s[nf][c]   * 0.125f;
                float sv1 = s[nf][2+c] * 0.125f;
                s[nf][c]   = (kg <= qg0) ? sv0 + slope*(float)(kg - qg0) : -1e30f;
                s[nf][2+c] = (kg <= qg1) ? sv1 + slope*(float)(kg - qg1) : -1e30f;
            }
        }

        // ---- online softmax ----
        float mx0 = -1e30f, mx1 = -1e30f;
        #pragma unroll
        for (int nf = 0; nf < 8; nf++) {
            mx0 = fmaxf(mx0, fmaxf(s[nf][0], s[nf][1]));
            mx1 = fmaxf(mx1, fmaxf(s[nf][2], s[nf][3]));
        }
        #pragma unroll
        for (int off = 1; off <= 2; off <<= 1) {
            mx0 = fmaxf(mx0, __shfl_xor_sync(0xffffffffu, mx0, off));
            mx1 = fmaxf(mx1, __shfl_xor_sync(0xffffffffu, mx1, off));
        }
        float mn0 = fmaxf(m0r, mx0), mn1 = fmaxf(m1r, mx1);
        float al0 = __expf(m0r - mn0), al1 = __expf(m1r - mn1);
        float rs0 = 0.f, rs1 = 0.f;
        #pragma unroll
        for (int nf = 0; nf < 8; nf++) {
            s[nf][0] = __expf(s[nf][0] - mn0);
            s[nf][1] = __expf(s[nf][1] - mn0);
            s[nf][2] = __expf(s[nf][2] - mn1);
            s[nf][3] = __expf(s[nf][3] - mn1);
            rs0 += s[nf][0] + s[nf][1];
            rs1 += s[nf][2] + s[nf][3];
        }
        #pragma unroll
        for (int off = 1; off <= 2; off <<= 1) {
            rs0 += __shfl_xor_sync(0xffffffffu, rs0, off);
            rs1 += __shfl_xor_sync(0xffffffffu, rs1, off);
        }
        l0s = l0s * al0 + rs0;
        l1s = l1s * al1 + rs1;
        m0r = mn0; m1r = mn1;

        #pragma unroll
        for (int nf = 0; nf < 8; nf++) {
            o[nf][0] *= al0; o[nf][1] *= al0;
            o[nf][2] *= al1; o[nf][3] *= al1;
        }

        // ---- O += P @ V (V row-major; B-frags via ldmatrix.trans) ----
        #pragma unroll
        for (int kk = 0; kk < 4; kk++) {
            uint32_t Ah[4], Al2[4];
            #pragma unroll
            for (int half = 0; half < 2; half++) {
                float* sv = s[2*kk + half];
                __nv_bfloat162 h01 = __floats2bfloat162_rn(sv[0], sv[1]);
                __nv_bfloat162 h23 = __floats2bfloat162_rn(sv[2], sv[3]);
                __nv_bfloat162 L01 = __floats2bfloat162_rn(
                    sv[0] - __bfloat162float(__low2bfloat16(h01)),
                    sv[1] - __bfloat162float(__high2bfloat16(h01)));
                __nv_bfloat162 L23 = __floats2bfloat162_rn(
                    sv[2] - __bfloat162float(__low2bfloat16(h23)),
                    sv[3] - __bfloat162float(__high2bfloat16(h23)));
                Ah[half*2 + 0] = *(uint32_t*)&h01;
                Ah[half*2 + 1] = *(uint32_t*)&h23;
                Al2[half*2 + 0] = *(uint32_t*)&L01;
                Al2[half*2 + 1] = *(uint32_t*)&L23;
            }
            #pragma unroll
            for (int np = 0; np < 4; np++) {
                uint32_t vb[4], vl2[4];
                // smem rows = key (k dim), cols = hd (n dim); trans-ldmatrix
                uint32_t off = ((kk*16 + (gq & 1)*8 + rr)*ALD + np*16 + (gq >> 1)*8) * 2;
                LDSM4T(vb, VH + off);
                LDSM4T(vl2, VL + off);
                MMA16816(o[np*2],   Ah,  vb[0], vb[1]);
                MMA16816(o[np*2],   Al2, vb[0], vb[1]);
                MMA16816(o[np*2],   Ah,  vl2[0], vl2[1]);
                MMA16816(o[np*2+1], Ah,  vb[2], vb[3]);
                MMA16816(o[np*2+1], Al2, vb[2], vb[3]);
                MMA16816(o[np*2+1], Ah,  vl2[2], vl2[3]);
            }
        }
    }

    // ---- epilogue ----
    float inv0 = 1.f / l0s, inv1 = 1.f / l1s;
    int row0 = b*SS + qt*64 + w*16 + (lane >> 2);
    int colb = h*HD + (lane & 3)*2;
    #pragma unroll
    for (int nf = 0; nf < 8; nf++) {
        float v0 = o[nf][0]*inv0, v1 = o[nf][1]*inv0;
        float v2 = o[nf][2]*inv1, v3 = o[nf][3]*inv1;
        size_t a0 = (size_t)row0 * DD + colb + nf*8;
        size_t a1 = (size_t)(row0 + 8) * DD + colb + nf*8;
        __nv_bfloat16 h0,h1,h2,h3,L0,L1,L2,L3;
        split1(v0, h0, L0); split1(v1, h1, L1);
        split1(v2, h2, L2); split1(v3, h3, L3);
        *(__nv_bfloat162*)(Ohi + a0) = __halves2bfloat162(h0, h1);
        *(__nv_bfloat162*)(Olo + a0) = __halves2bfloat162(L0, L1);
        *(__nv_bfloat162*)(Ohi + a1) = __halves2bfloat162(h2, h3);
        *(__nv_bfloat162*)(Olo + a1) = __halves2bfloat162(L2, L3);
    }
}

// ---------------- embedding lookup ----------------
__global__ void embed_kernel(const int* __restrict__ tokens,
                             const float* __restrict__ emb,
                             float* __restrict__ x) {
    int row = blockIdx.x;
    int tok = tokens[row];
    const float4* src = (const float4*)(emb + (size_t)tok * DD);
    float4* dst = (float4*)(x + (size_t)row * DD);
    for (int i = threadIdx.x; i < DD/4; i += blockDim.x) dst[i] = src[i];
}

// ---------------- layernorm -> bf16 hi/lo planes ----------------
__global__ void ln_kernel(const float* __restrict__ x,
                          const float* __restrict__ gw,
                          const float* __restrict__ bw,
                          __nv_bfloat16* __restrict__ hi,
                          __nv_bfloat16* __restrict__ lo) {
    int row = blockIdx.x;
    const float* xr = x + (size_t)row * DD;
    float s = 0.f, s2 = 0.f;
    for (int i = threadIdx.x; i < DD; i += 256) {
        float v = xr[i];
        s += v;
        s2 = fmaf(v, v, s2);
    }
    __shared__ float rs[8], rs2[8];
    #pragma unroll
    for (int o = 16; o > 0; o >>= 1) {
        s  += __shfl_down_sync(0xffffffffu, s,  o);
        s2 += __shfl_down_sync(0xffffffffu, s2, o);
    }
    int w = threadIdx.x >> 5;
    if ((threadIdx.x & 31) == 0) { rs[w] = s; rs2[w] = s2; }
    __syncthreads();
    __shared__ float mean_s, rstd_s;
    if (threadIdx.x == 0) {
        float ts = 0.f, ts2 = 0.f;
        #pragma unroll
        for (int i = 0; i < 8; i++) { ts += rs[i]; ts2 += rs2[i]; }
        float m = ts / (float)DD;
        float var = ts2 / (float)DD - m * m;
        mean_s = m;
        rstd_s = rsqrtf(var + 1e-5f);
    }
    __syncthreads();
    float m = mean_s, r = rstd_s;
    __nv_bfloat16* hrow = hi + (size_t)row * DD;
    __nv_bfloat16* lrow = lo + (size_t)row * DD;
    for (int i = threadIdx.x; i < DD; i += 256) {
        float v = (xr[i] - m) * r * gw[i] + bw[i];
        __nv_bfloat16 vh, vl;
        split1(v, vh, vl);
        hrow[i] = vh;
        lrow[i] = vl;
    }
}

// ---------------- SwiGLU from packed ff planes -> bf16 hi/lo --------------
__global__ void swiglu_kernel(const __nv_bfloat16* __restrict__ fh,
                              const __nv_bfloat16* __restrict__ fl,
                              __nv_bfloat16* __restrict__ hi,
                              __nv_bfloat16* __restrict__ lo) {
    int i = blockIdx.x * 256 + threadIdx.x;   // over MM*DD/4 quads
    int row = i / (DD/4);
    int c4 = (i % (DD/4)) * 4;
    size_t fa = (size_t)row * FFS + c4;
    ushort4 ah4 = *(const ushort4*)(fh + fa);
    ushort4 al4 = *(const ushort4*)(fl + fa);
    ushort4 ch4 = *(const ushort4*)(fh + fa + DD);
    ushort4 cl4 = *(const ushort4*)(fl + fa + DD);
    float x0 = __bfloat162float(__ushort_as_bfloat16(ah4.x)) + __bfloat162float(__ushort_as_bfloat16(al4.x));
    float x1 = __bfloat162float(__ushort_as_bfloat16(ah4.y)) + __bfloat162float(__ushort_as_bfloat16(al4.y));
    float x2 = __bfloat162float(__ushort_as_bfloat16(ah4.z)) + __bfloat162float(__ushort_as_bfloat16(al4.z));
    float x3 = __bfloat162float(__ushort_as_bfloat16(ah4.w)) + __bfloat162float(__ushort_as_bfloat16(al4.w));
    float c0 = __bfloat162float(__ushort_as_bfloat16(ch4.x)) + __bfloat162float(__ushort_as_bfloat16(cl4.x));
    float c1 = __bfloat162float(__ushort_as_bfloat16(ch4.y)) + __bfloat162float(__ushort_as_bfloat16(cl4.y));
    float c2 = __bfloat162float(__ushort_as_bfloat16(ch4.z)) + __bfloat162float(__ushort_as_bfloat16(cl4.z));
    float c3 = __bfloat162float(__ushort_as_bfloat16(ch4.w)) + __bfloat162float(__ushort_as_bfloat16(cl4.w));
    float r0 = x0 / (1.f + __expf(-x0)) * c0;
    float r1 = x1 / (1.f + __expf(-x1)) * c1;
    float r2 = x2 / (1.f + __expf(-x2)) * c2;
    float r3 = x3 / (1.f + __expf(-x3)) * c3;
    __nv_bfloat16 h0,h1,h2,h3,l0,l1,l2,l3;
    split1(r0, h0, l0); split1(r1, h1, l1);
    split1(r2, h2, l2); split1(r3, h3, l3);
    size_t oa = (size_t)row * DD + c4;
    *(ushort4*)(hi + oa) = make_ushort4(__bfloat16_as_ushort(h0), __bfloat16_as_ushort(h1),
                                        __bfloat16_as_ushort(h2), __bfloat16_as_ushort(h3));
    *(ushort4*)(lo + oa) = make_ushort4(__bfloat16_as_ushort(l0), __bfloat16_as_ushort(l1),
                                        __bfloat16_as_ushort(l2), __bfloat16_as_ushort(l3));
}

// ---------------- launch ----------------
extern "C" void kernel_launch(void* const* d_in, const int* in_sizes, int n_in,
                              void* d_out, int out_size) {
    const int*   tokens = (const int*)d_in[0];
    const float* emb    = (const float*)d_in[1];
    const float* wq     = (const float*)d_in[2];
    const float* wk     = (const float*)d_in[3];
    const float* wv     = (const float*)d_in[4];
    const float* wo     = (const float*)d_in[5];
    const float* ln1_g  = (const float*)d_in[6];
    const float* ln1_b  = (const float*)d_in[7];
    const float* ln2_g  = (const float*)d_in[8];
    const float* ln2_b  = (const float*)d_in[9];
    const float* w1     = (const float*)d_in[10];
    const float* w2     = (const float*)d_in[11];
    const float* w3     = (const float*)d_in[12];
    const float* lnf_g  = (const float*)d_in[13];
    const float* lnf_b  = (const float*)d_in[14];
    const float* w_out  = (const float*)d_in[15];
    float* out = (float*)d_out;

    float* px;
    cudaGetSymbolAddress((void**)&px, g_x);
    __nv_bfloat16 *whi, *wlo, *ahi, *alo, *qkvh, *qkvl, *ffh, *ffl;
    cudaGetSymbolAddress((void**)&whi, g_whi);
    cudaGetSymbolAddress((void**)&wlo, g_wlo);
    cudaGetSymbolAddress((void**)&ahi, g_ahi);
    cudaGetSymbolAddress((void**)&alo, g_alo);
    cudaGetSymbolAddress((void**)&qkvh, g_qkvh);
    cudaGetSymbolAddress((void**)&qkvl, g_qkvl);
    cudaGetSymbolAddress((void**)&ffh, g_ffh);
    cudaGetSymbolAddress((void**)&ffl, g_ffl);

    cudaFuncSetAttribute(attn_mma,
                         cudaFuncAttributeMaxDynamicSharedMemorySize, ASMEM);
    cudaFuncSetAttribute(gemm_mma<false,true>,
                         cudaFuncAttributeMaxDynamicSharedMemorySize, GSMEM);
    cudaFuncSetAttribute(gemm_mma<true,false>,
                         cudaFuncAttributeMaxDynamicSharedMemorySize, GSMEM);
    cudaFuncSetAttribute(gemm_mma<false,false>,
                         cudaFuncAttributeMaxDynamicSharedMemorySize, GSMEM);

    // ---- convert weights to bf16 hi/lo planes (packed layouts) ----
    {
        int n4 = WMAT / 4;
        for (int l = 0; l < LL; l++) {
            size_t so = (size_t)l * WMAT;
            size_t qo = QKV_OFF + (size_t)l * 3 * WMAT;
            conv_split<<<n4/256, 256>>>(wq + so, whi + qo,          wlo + qo,          n4);
            conv_split<<<n4/256, 256>>>(wk + so, whi + qo + WMAT,   wlo + qo + WMAT,   n4);
            conv_split<<<n4/256, 256>>>(wv + so, whi + qo + 2*WMAT, wlo + qo + 2*WMAT, n4);
            size_t fo = W13_OFF + (size_t)l * 2 * WMAT;
            conv_split<<<n4/256, 256>>>(w1 + so, whi + fo,          wlo + fo,          n4);
            conv_split<<<n4/256, 256>>>(w3 + so, whi + fo + WMAT,   wlo + fo + WMAT,   n4);
        }
        int n4L = (LL * WMAT) / 4;
        conv_split<<<n4L/256, 256>>>(wo, whi + WO_OFF, wlo + WO_OFF, n4L);
        conv_split<<<n4L/256, 256>>>(w2, whi + W2_OFF, wlo + W2_OFF, n4L);
        int n4o = (VV * DD) / 4;
        conv_split<<<n4o/256, 256>>>(w_out, whi + WOUT_OFF, wlo + WOUT_OFF, n4o);
    }

    embed_kernel<<<MM, 256>>>(tokens, emb, px);

    dim3 gQKV(QKVS/128, MM/128);
    dim3 gD(DD/128, MM/128);
    dim3 gFF(FFS/128, MM/128);
    for (int l = 0; l < LL; l++) {
        size_t qo = QKV_OFF + (size_t)l * 3 * WMAT;
        size_t oo = WO_OFF + (size_t)l * WMAT;
        size_t fo = W13_OFF + (size_t)l * 2 * WMAT;
        size_t to = W2_OFF + (size_t)l * WMAT;

        // attention
        ln_kernel<<<MM, 256>>>(px, ln1_g + l*DD, ln1_b + l*DD, ahi, alo);
        gemm_mma<false,true><<<gQKV, 256, GSMEM>>>(ahi, alo, whi + qo, wlo + qo,
                                                   nullptr, nullptr, qkvh, qkvl, QKVS, DD);
        attn_mma<<<dim3(SS/64, BB*HH), 128, ASMEM>>>(qkvh, qkvl, ahi, alo);
        gemm_mma<true,false><<<gD, 256, GSMEM>>>(ahi, alo, whi + oo, wlo + oo,
                                                 px, px, nullptr, nullptr, DD, DD);

        // SwiGLU FFN
        ln_kernel<<<MM, 256>>>(px, ln2_g + l*DD, ln2_b + l*DD, ahi, alo);
        gemm_mma<false,true><<<gFF, 256, GSMEM>>>(ahi, alo, whi + fo, wlo + fo,
                                                  nullptr, nullptr, ffh, ffl, FFS, DD);
        swiglu_kernel<<<(MM*DD/4)/256, 256>>>(ffh, ffl, ahi, alo);
        gemm_mma<true,false><<<gD, 256, GSMEM>>>(ahi, alo, whi + to, wlo + to,
                                                 px, px, nullptr, nullptr, DD, DD);
    }

    // final LN + logits
    ln_kernel<<<MM, 256>>>(px, lnf_g, lnf_b, ahi, alo);
    gemm_mma<false,false><<<dim3(VV/128, MM/128), 256, GSMEM>>>(
        ahi, alo, whi + WOUT_OFF, wlo + WOUT_OFF, nullptr, out, nullptr, nullptr, VV, DD);
}